// round 1
// baseline (speedup 1.0000x reference)
#include <cuda_runtime.h>
#include <math.h>

#define D_MODEL   1024
#define HIDDEN    4096
#define N_EXPERTS 8
#define T_TOKENS  16384
#define MAX_ROWS  (T_TOKENS * 2)

#define BM 128
#define BN 128
#define BK 16
#define TM 8
#define TN 8

// ---------------- scratch (static device globals; no allocs) ----------------
__device__ int   g_count[N_EXPERTS];
__device__ int   g_offset[N_EXPERTS];
__device__ int   g_tok[N_EXPERTS * T_TOKENS];
__device__ float g_wt [N_EXPERTS * T_TOKENS];
__device__ float g_h  [(size_t)MAX_ROWS * HIDDEN];   // 512 MB compact h buffer

// ---------------- kernel 0: zero output + routing counters ----------------
__global__ void zero_kernel(float4* out, int n4) {
    int i = blockIdx.x * blockDim.x + threadIdx.x;
    if (i < n4) out[i] = make_float4(0.f, 0.f, 0.f, 0.f);
    if (i < N_EXPERTS) g_count[i] = 0;
}

// ---------------- kernel 1: gating (one warp per token) ----------------
__global__ void gate_kernel(const float* __restrict__ x,
                            const float* __restrict__ gw) {
    int gtid = blockIdx.x * blockDim.x + threadIdx.x;
    int warp = gtid >> 5;
    int lane = gtid & 31;
    if (warp >= T_TOKENS) return;

    const float* xr = x + (size_t)warp * D_MODEL;
    float acc[N_EXPERTS];
#pragma unroll
    for (int e = 0; e < N_EXPERTS; e++) acc[e] = 0.f;

    for (int d = lane; d < D_MODEL; d += 32) {
        float xv = xr[d];
        float4 g0 = *(const float4*)(gw + d * N_EXPERTS);
        float4 g1 = *(const float4*)(gw + d * N_EXPERTS + 4);
        acc[0] += xv * g0.x; acc[1] += xv * g0.y;
        acc[2] += xv * g0.z; acc[3] += xv * g0.w;
        acc[4] += xv * g1.x; acc[5] += xv * g1.y;
        acc[6] += xv * g1.z; acc[7] += xv * g1.w;
    }
#pragma unroll
    for (int off = 16; off > 0; off >>= 1)
#pragma unroll
        for (int e = 0; e < N_EXPERTS; e++)
            acc[e] += __shfl_xor_sync(0xffffffffu, acc[e], off);

    if (lane == 0) {
        // top-1 (strict > keeps lowest index on ties, matching lax.top_k)
        int i0 = 0; float m0 = acc[0];
#pragma unroll
        for (int e = 1; e < N_EXPERTS; e++)
            if (acc[e] > m0) { m0 = acc[e]; i0 = e; }
        // top-2
        int i1 = -1; float m1 = -1e30f;
#pragma unroll
        for (int e = 0; e < N_EXPERTS; e++)
            if (e != i0 && acc[e] > m1) { m1 = acc[e]; i1 = e; }

        float ex = expf(m1 - m0);           // <= 1
        float w0 = 1.0f / (1.0f + ex);
        float w1 = ex / (1.0f + ex);

        int p0 = atomicAdd(&g_count[i0], 1);
        g_tok[i0 * T_TOKENS + p0] = warp;
        g_wt [i0 * T_TOKENS + p0] = w0;
        int p1 = atomicAdd(&g_count[i1], 1);
        g_tok[i1 * T_TOKENS + p1] = warp;
        g_wt [i1 * T_TOKENS + p1] = w1;
    }
}

// ---------------- kernel 2: exclusive scan over 8 counts ----------------
__global__ void scan_kernel() {
    if (threadIdx.x == 0) {
        int s = 0;
        for (int e = 0; e < N_EXPERTS; e++) { g_offset[e] = s; s += g_count[e]; }
    }
}

// ---------------- kernel 3: grouped GEMM1 + SiLU -> g_h ----------------
// h[rows_of_e, HIDDEN] = silu( gather(x) @ w1[e] ), K = D_MODEL
__global__ void __launch_bounds__(256, 2)
gemm1_silu_kernel(const float* __restrict__ x, const float* __restrict__ w1) {
    const int e     = blockIdx.z;
    const int mcnt  = g_count[e];
    const int mbase = blockIdx.y * BM;
    if (mbase >= mcnt) return;
    const int nbase = blockIdx.x * BN;

    const float* __restrict__ W   = w1 + (size_t)e * D_MODEL * HIDDEN; // [K,N]
    const int*   __restrict__ tks = g_tok + e * T_TOKENS;
    const int hoff = g_offset[e];

    __shared__ float As[2][BK][BM];
    __shared__ float Bs[2][BK][BN];

    const int tid = threadIdx.x;
    const int tx = tid & 15;
    const int ty = tid >> 4;

    // A-load tasks (2 per thread): task q -> row=q>>2, kcol=(q&3)*4
    const int ar0 = tid >> 2,         ak0 = (tid & 3) * 4;
    const int ar1 = (tid + 256) >> 2, ak1 = (tid & 3) * 4;  // (tid+256)&3 == tid&3
    const int gm0 = mbase + ar0, gm1 = mbase + ar1;
    const bool av0 = gm0 < mcnt, av1 = gm1 < mcnt;
    const float* ap0 = av0 ? (x + (size_t)tks[gm0] * D_MODEL) : x;
    const float* ap1 = av1 ? (x + (size_t)tks[gm1] * D_MODEL) : x;

    // B-load tasks: task q -> krow=q>>5, ncol=(q&31)*4
    const int bk0 = tid >> 5,         bn0 = (tid & 31) * 4;
    const int bk1 = (tid + 256) >> 5, bn1 = bn0;

    float acc[TM][TN];
#pragma unroll
    for (int i = 0; i < TM; i++)
#pragma unroll
        for (int j = 0; j < TN; j++) acc[i][j] = 0.f;

    const int NT = D_MODEL / BK; // 64
    float4 a0, a1, b0, b1;

    // prefetch tile 0
    a0 = av0 ? *(const float4*)(ap0 + ak0) : make_float4(0,0,0,0);
    a1 = av1 ? *(const float4*)(ap1 + ak1) : make_float4(0,0,0,0);
    b0 = *(const float4*)(W + (size_t)bk0 * HIDDEN + nbase + bn0);
    b1 = *(const float4*)(W + (size_t)bk1 * HIDDEN + nbase + bn1);
    As[0][ak0+0][ar0] = a0.x; As[0][ak0+1][ar0] = a0.y;
    As[0][ak0+2][ar0] = a0.z; As[0][ak0+3][ar0] = a0.w;
    As[0][ak1+0][ar1] = a1.x; As[0][ak1+1][ar1] = a1.y;
    As[0][ak1+2][ar1] = a1.z; As[0][ak1+3][ar1] = a1.w;
    *(float4*)&Bs[0][bk0][bn0] = b0;
    *(float4*)&Bs[0][bk1][bn1] = b1;
    __syncthreads();

    for (int kt = 0; kt < NT; kt++) {
        const int cur = kt & 1;
        if (kt + 1 < NT) {
            const int k0 = (kt + 1) * BK;
            a0 = av0 ? *(const float4*)(ap0 + k0 + ak0) : make_float4(0,0,0,0);
            a1 = av1 ? *(const float4*)(ap1 + k0 + ak1) : make_float4(0,0,0,0);
            b0 = *(const float4*)(W + (size_t)(k0 + bk0) * HIDDEN + nbase + bn0);
            b1 = *(const float4*)(W + (size_t)(k0 + bk1) * HIDDEN + nbase + bn1);
        }
#pragma unroll
        for (int k = 0; k < BK; k++) {
            float ar[TM], br[TN];
            *(float4*)&ar[0] = *(const float4*)&As[cur][k][ty * TM];
            *(float4*)&ar[4] = *(const float4*)&As[cur][k][ty * TM + 4];
            *(float4*)&br[0] = *(const float4*)&Bs[cur][k][tx * TN];
            *(float4*)&br[4] = *(const float4*)&Bs[cur][k][tx * TN + 4];
#pragma unroll
            for (int i = 0; i < TM; i++)
#pragma unroll
                for (int j = 0; j < TN; j++)
                    acc[i][j] += ar[i] * br[j];
        }
        if (kt + 1 < NT) {
            const int nxt = cur ^ 1;
            As[nxt][ak0+0][ar0] = a0.x; As[nxt][ak0+1][ar0] = a0.y;
            As[nxt][ak0+2][ar0] = a0.z; As[nxt][ak0+3][ar0] = a0.w;
            As[nxt][ak1+0][ar1] = a1.x; As[nxt][ak1+1][ar1] = a1.y;
            As[nxt][ak1+2][ar1] = a1.z; As[nxt][ak1+3][ar1] = a1.w;
            *(float4*)&Bs[nxt][bk0][bn0] = b0;
            *(float4*)&Bs[nxt][bk1][bn1] = b1;
        }
        __syncthreads();
    }

    // epilogue: SiLU, store to compact h rows
#pragma unroll
    for (int i = 0; i < TM; i++) {
        const int gm = mbase + ty * TM + i;
        if (gm >= mcnt) break;
        float* hp = g_h + (size_t)(hoff + gm) * HIDDEN + nbase + tx * TN;
        float v[TN];
#pragma unroll
        for (int j = 0; j < TN; j++) {
            float a = acc[i][j];
            v[j] = a / (1.0f + __expf(-a));
        }
        *(float4*)(hp)     = make_float4(v[0], v[1], v[2], v[3]);
        *(float4*)(hp + 4) = make_float4(v[4], v[5], v[6], v[7]);
    }
}

// ---------------- kernel 4: grouped GEMM2 + weighted scatter-add ----------------
// out[tok] += wt * ( h_rows_of_e @ w2[e] ), K = HIDDEN
__global__ void __launch_bounds__(256, 2)
gemm2_scatter_kernel(const float* __restrict__ w2, float* __restrict__ out) {
    const int e     = blockIdx.z;
    const int mcnt  = g_count[e];
    const int mbase = blockIdx.y * BM;
    if (mbase >= mcnt) return;
    const int nbase = blockIdx.x * BN;

    const float* __restrict__ W   = w2 + (size_t)e * HIDDEN * D_MODEL; // [K,N]
    const int*   __restrict__ tks = g_tok + e * T_TOKENS;
    const float* __restrict__ wts = g_wt + e * T_TOKENS;
    const int hoff = g_offset[e];

    __shared__ float As[2][BK][BM];
    __shared__ float Bs[2][BK][BN];

    const int tid = threadIdx.x;
    const int tx = tid & 15;
    const int ty = tid >> 4;

    const int ar0 = tid >> 2,         ak0 = (tid & 3) * 4;
    const int ar1 = (tid + 256) >> 2, ak1 = (tid & 3) * 4;
    const int gm0 = mbase + ar0, gm1 = mbase + ar1;
    const bool av0 = gm0 < mcnt, av1 = gm1 < mcnt;
    const float* ap0 = g_h + (size_t)(hoff + (av0 ? gm0 : 0)) * HIDDEN;
    const float* ap1 = g_h + (size_t)(hoff + (av1 ? gm1 : 0)) * HIDDEN;

    const int bk0 = tid >> 5,         bn0 = (tid & 31) * 4;
    const int bk1 = (tid + 256) >> 5, bn1 = bn0;

    float acc[TM][TN];
#pragma unroll
    for (int i = 0; i < TM; i++)
#pragma unroll
        for (int j = 0; j < TN; j++) acc[i][j] = 0.f;

    const int NT = HIDDEN / BK; // 256
    float4 a0, a1, b0, b1;

    a0 = av0 ? *(const float4*)(ap0 + ak0) : make_float4(0,0,0,0);
    a1 = av1 ? *(const float4*)(ap1 + ak1) : make_float4(0,0,0,0);
    b0 = *(const float4*)(W + (size_t)bk0 * D_MODEL + nbase + bn0);
    b1 = *(const float4*)(W + (size_t)bk1 * D_MODEL + nbase + bn1);
    As[0][ak0+0][ar0] = a0.x; As[0][ak0+1][ar0] = a0.y;
    As[0][ak0+2][ar0] = a0.z; As[0][ak0+3][ar0] = a0.w;
    As[0][ak1+0][ar1] = a1.x; As[0][ak1+1][ar1] = a1.y;
    As[0][ak1+2][ar1] = a1.z; As[0][ak1+3][ar1] = a1.w;
    *(float4*)&Bs[0][bk0][bn0] = b0;
    *(float4*)&Bs[0][bk1][bn1] = b1;
    __syncthreads();

    for (int kt = 0; kt < NT; kt++) {
        const int cur = kt & 1;
        if (kt + 1 < NT) {
            const int k0 = (kt + 1) * BK;
            a0 = av0 ? *(const float4*)(ap0 + k0 + ak0) : make_float4(0,0,0,0);
            a1 = av1 ? *(const float4*)(ap1 + k0 + ak1) : make_float4(0,0,0,0);
            b0 = *(const float4*)(W + (size_t)(k0 + bk0) * D_MODEL + nbase + bn0);
            b1 = *(const float4*)(W + (size_t)(k0 + bk1) * D_MODEL + nbase + bn1);
        }
#pragma unroll
        for (int k = 0; k < BK; k++) {
            float ar[TM], br[TN];
            *(float4*)&ar[0] = *(const float4*)&As[cur][k][ty * TM];
            *(float4*)&ar[4] = *(const float4*)&As[cur][k][ty * TM + 4];
            *(float4*)&br[0] = *(const float4*)&Bs[cur][k][tx * TN];
            *(float4*)&br[4] = *(const float4*)&Bs[cur][k][tx * TN + 4];
#pragma unroll
            for (int i = 0; i < TM; i++)
#pragma unroll
                for (int j = 0; j < TN; j++)
                    acc[i][j] += ar[i] * br[j];
        }
        if (kt + 1 < NT) {
            const int nxt = cur ^ 1;
            As[nxt][ak0+0][ar0] = a0.x; As[nxt][ak0+1][ar0] = a0.y;
            As[nxt][ak0+2][ar0] = a0.z; As[nxt][ak0+3][ar0] = a0.w;
            As[nxt][ak1+0][ar1] = a1.x; As[nxt][ak1+1][ar1] = a1.y;
            As[nxt][ak1+2][ar1] = a1.z; As[nxt][ak1+3][ar1] = a1.w;
            *(float4*)&Bs[nxt][bk0][bn0] = b0;
            *(float4*)&Bs[nxt][bk1][bn1] = b1;
        }
        __syncthreads();
    }

    // epilogue: weighted atomic scatter-add into out
#pragma unroll
    for (int i = 0; i < TM; i++) {
        const int gm = mbase + ty * TM + i;
        if (gm >= mcnt) break;
        const int tok = tks[gm];
        const float w = wts[gm];
        float* op = out + (size_t)tok * D_MODEL + nbase + tx * TN;
#pragma unroll
        for (int j = 0; j < TN; j++)
            atomicAdd(op + j, w * acc[i][j]);
    }
}

// ---------------- launch ----------------
extern "C" void kernel_launch(void* const* d_in, const int* in_sizes, int n_in,
                              void* d_out, int out_size) {
    const float* x  = (const float*)d_in[0];
    const float* gw = (const float*)d_in[1];
    const float* w1 = (const float*)d_in[2];
    const float* w2 = (const float*)d_in[3];
    float* out = (float*)d_out;

    int n4 = out_size / 4; // 4,194,304 float4
    zero_kernel<<<(n4 + 255) / 256, 256>>>((float4*)out, n4);
    gate_kernel<<<T_TOKENS / 8, 256>>>(x, gw);
    scan_kernel<<<1, 32>>>();

    dim3 g1(HIDDEN / BN, T_TOKENS / BM, N_EXPERTS);   // (32, 128, 8)
    gemm1_silu_kernel<<<g1, 256>>>(x, w1);

    dim3 g2(D_MODEL / BN, T_TOKENS / BM, N_EXPERTS);  // (8, 128, 8)
    gemm2_scatter_kernel<<<g2, 256>>>(w2, out);
}

// round 3
// speedup vs baseline: 3.5755x; 3.5755x over previous
#include <cuda_runtime.h>
#include <math.h>
#include <stdint.h>

#define D_MODEL   1024
#define HIDDEN    4096
#define N_EXPERTS 8
#define T_TOKENS  16384
#define MAX_ROWS  (T_TOKENS * 2)

// tile config
#define TILE_M 128
#define TILE_N 128
#define TBK    32
#define PADF   36                 // padded row stride in floats (144 B)
#define ROWB   144
#define ABUF   (128 * ROWB)       // 18432 B per buffer per matrix
#define SMEM_A 0
#define SMEM_B (2 * ABUF)         // 36864
#define SMEM_TOTAL (4 * ABUF)     // 73728 B

// ---------------- scratch ----------------
__device__ int   g_count[N_EXPERTS];
__device__ int   g_offset[N_EXPERTS];
__device__ int   g_tok[N_EXPERTS * T_TOKENS];
__device__ float g_wt [N_EXPERTS * T_TOKENS];
__device__ float g_h  [(size_t)MAX_ROWS * HIDDEN];            // tf32-rounded h
__device__ float g_xr [(size_t)T_TOKENS * D_MODEL];           // tf32-rounded x
__device__ float g_w1t[(size_t)N_EXPERTS * HIDDEN * D_MODEL]; // [E][N=4096][K=1024]
__device__ float g_w2t[(size_t)N_EXPERTS * D_MODEL * HIDDEN]; // [E][N=1024][K=4096]

// ---------------- helpers ----------------
__device__ __forceinline__ uint32_t smem_u32(const void* p) {
    uint32_t a;
    asm("{ .reg .u64 t; cvta.to.shared.u64 t, %1; cvt.u32.u64 %0, t; }" : "=r"(a) : "l"(p));
    return a;
}
__device__ __forceinline__ float to_tf32(float f) {
    uint32_t u;
    asm("cvt.rna.tf32.f32 %0, %1;" : "=r"(u) : "f"(f));
    return __uint_as_float(u);
}
#define CP_ASYNC16(dst, src) \
    asm volatile("cp.async.cg.shared.global [%0], [%1], 16;" :: "r"(dst), "l"(src))
#define CP_COMMIT() asm volatile("cp.async.commit_group;" ::: "memory")
#define CP_WAIT1()  asm volatile("cp.async.wait_group 1;" ::: "memory")
#define CP_WAIT0()  asm volatile("cp.async.wait_group 0;" ::: "memory")

__device__ __forceinline__ void mma_tf32(float* d, const uint32_t* a, const uint32_t* b) {
    asm volatile(
        "mma.sync.aligned.m16n8k8.row.col.f32.tf32.tf32.f32 "
        "{%0,%1,%2,%3}, {%4,%5,%6,%7}, {%8,%9}, {%0,%1,%2,%3};"
        : "+f"(d[0]), "+f"(d[1]), "+f"(d[2]), "+f"(d[3])
        : "r"(a[0]), "r"(a[1]), "r"(a[2]), "r"(a[3]), "r"(b[0]), "r"(b[1]));
}

// ---------------- kernel 0: zero output + counters ----------------
__global__ void zero_kernel(float4* out, int n4) {
    int i = blockIdx.x * blockDim.x + threadIdx.x;
    if (i < n4) out[i] = make_float4(0.f, 0.f, 0.f, 0.f);
    if (i < N_EXPERTS) g_count[i] = 0;
}

// ---------------- kernel 0b: round x to tf32 ----------------
__global__ void round_x_kernel(const float* __restrict__ x) {
    int i = blockIdx.x * blockDim.x + threadIdx.x;
    if (i < T_TOKENS * D_MODEL) g_xr[i] = to_tf32(x[i]);
}

// ---------------- kernel 0c: transpose weights (+ tf32 round) ----------------
__global__ void transpose_w_kernel(const float* __restrict__ w1, const float* __restrict__ w2) {
    __shared__ float tile[32][33];
    const int z = blockIdx.z;
    const float* src; float* dst; int R, C;
    if (z < N_EXPERTS) {
        src = w1 + (size_t)z * D_MODEL * HIDDEN; dst = g_w1t + (size_t)z * HIDDEN * D_MODEL;
        R = D_MODEL; C = HIDDEN;
    } else {
        src = w2 + (size_t)(z - N_EXPERTS) * HIDDEN * D_MODEL;
        dst = g_w2t + (size_t)(z - N_EXPERTS) * D_MODEL * HIDDEN;
        R = HIDDEN; C = D_MODEL;
    }
    const int c0 = blockIdx.x * 32, r0 = blockIdx.y * 32;
    if (c0 >= C || r0 >= R) return;
    const int tx = threadIdx.x, ty = threadIdx.y;
#pragma unroll
    for (int j = 0; j < 32; j += 8)
        tile[ty + j][tx] = to_tf32(src[(size_t)(r0 + ty + j) * C + c0 + tx]);
    __syncthreads();
#pragma unroll
    for (int j = 0; j < 32; j += 8)
        dst[(size_t)(c0 + ty + j) * R + r0 + tx] = tile[tx][ty + j];
}

// ---------------- kernel 1: gating ----------------
__global__ void gate_kernel(const float* __restrict__ x, const float* __restrict__ gw) {
    int gtid = blockIdx.x * blockDim.x + threadIdx.x;
    int warp = gtid >> 5;
    int lane = gtid & 31;
    if (warp >= T_TOKENS) return;

    const float* xr = x + (size_t)warp * D_MODEL;
    float acc[N_EXPERTS];
#pragma unroll
    for (int e = 0; e < N_EXPERTS; e++) acc[e] = 0.f;
    for (int d = lane; d < D_MODEL; d += 32) {
        float xv = xr[d];
        float4 g0 = *(const float4*)(gw + d * N_EXPERTS);
        float4 g1 = *(const float4*)(gw + d * N_EXPERTS + 4);
        acc[0] += xv * g0.x; acc[1] += xv * g0.y; acc[2] += xv * g0.z; acc[3] += xv * g0.w;
        acc[4] += xv * g1.x; acc[5] += xv * g1.y; acc[6] += xv * g1.z; acc[7] += xv * g1.w;
    }
#pragma unroll
    for (int off = 16; off > 0; off >>= 1)
#pragma unroll
        for (int e = 0; e < N_EXPERTS; e++)
            acc[e] += __shfl_xor_sync(0xffffffffu, acc[e], off);

    if (lane == 0) {
        int i0 = 0; float m0 = acc[0];
#pragma unroll
        for (int e = 1; e < N_EXPERTS; e++) if (acc[e] > m0) { m0 = acc[e]; i0 = e; }
        int i1 = -1; float m1 = -1e30f;
#pragma unroll
        for (int e = 0; e < N_EXPERTS; e++) if (e != i0 && acc[e] > m1) { m1 = acc[e]; i1 = e; }
        float ex = expf(m1 - m0);
        float w0 = 1.0f / (1.0f + ex);
        float w1v = ex / (1.0f + ex);
        int p0 = atomicAdd(&g_count[i0], 1);
        g_tok[i0 * T_TOKENS + p0] = warp; g_wt[i0 * T_TOKENS + p0] = w0;
        int p1 = atomicAdd(&g_count[i1], 1);
        g_tok[i1 * T_TOKENS + p1] = warp; g_wt[i1 * T_TOKENS + p1] = w1v;
    }
}

__global__ void scan_kernel() {
    if (threadIdx.x == 0) {
        int s = 0;
        for (int e = 0; e < N_EXPERTS; e++) { g_offset[e] = s; s += g_count[e]; }
    }
}

// ============================================================================
// tf32 mma.sync grouped GEMM core (shared by GEMM1/GEMM2 via macro-ish device fn)
// A: gathered rows, K-major. B: transposed weights [N][K]. C tile 128x128.
// 256 threads = 8 warps (2 M x 4 N), warp tile 64x32 = 4x4 m16n8k8.
// ============================================================================
struct GemmCtx {
    const float* aptr[4];
    const float* bptr[4];
    uint32_t dA[4], dB[4];
};

__device__ __forceinline__ void gemm_mainloop(
    const char* smem_raw, const GemmCtx& ctx, int NT,
    float acc[4][4][4], int wid, int lane)
{
    const int warpM = wid & 1, warpN = wid >> 1;
    const uint32_t abase = (uint32_t)(warpM * 64 + (lane >> 2)) * PADF + (lane & 3);
    const uint32_t bbase = (uint32_t)(warpN * 32 + (lane >> 2)) * PADF + (lane & 3);

    // prologue: buffer 0
#pragma unroll
    for (int i = 0; i < 4; i++) {
        CP_ASYNC16(ctx.dA[i], ctx.aptr[i]);
        CP_ASYNC16(ctx.dB[i], ctx.bptr[i]);
    }
    CP_COMMIT();

    for (int kt = 0; kt < NT; kt++) {
        const int buf = kt & 1;
        if (kt + 1 < NT) {
            const uint32_t off = (uint32_t)(buf ^ 1) * ABUF;
#pragma unroll
            for (int i = 0; i < 4; i++) {
                CP_ASYNC16(ctx.dA[i] + off, ctx.aptr[i] + (kt + 1) * TBK);
                CP_ASYNC16(ctx.dB[i] + off, ctx.bptr[i] + (kt + 1) * TBK);
            }
            CP_COMMIT();
            CP_WAIT1();
        } else {
            CP_WAIT0();
        }
        __syncthreads();

        const uint32_t* SA = (const uint32_t*)(smem_raw + SMEM_A + buf * ABUF);
        const uint32_t* SB = (const uint32_t*)(smem_raw + SMEM_B + buf * ABUF);
#pragma unroll
        for (int ks = 0; ks < 4; ks++) {
            uint32_t a[4][4], b[4][2];
#pragma unroll
            for (int mi = 0; mi < 4; mi++) {
                uint32_t ix = abase + (uint32_t)mi * 16 * PADF + ks * 8;
                a[mi][0] = SA[ix];
                a[mi][1] = SA[ix + 8 * PADF];
                a[mi][2] = SA[ix + 4];
                a[mi][3] = SA[ix + 8 * PADF + 4];
            }
#pragma unroll
            for (int ni = 0; ni < 4; ni++) {
                uint32_t ix = bbase + (uint32_t)ni * 8 * PADF + ks * 8;
                b[ni][0] = SB[ix];
                b[ni][1] = SB[ix + 4];
            }
#pragma unroll
            for (int mi = 0; mi < 4; mi++)
#pragma unroll
                for (int ni = 0; ni < 4; ni++)
                    mma_tf32(acc[mi][ni], a[mi], b[ni]);
        }
        __syncthreads();   // protect buf before next-stage cp.async overwrites it
    }
}

// ---------------- kernel 3: GEMM1 + SiLU -> g_h ----------------
__global__ void __launch_bounds__(256, 2)
gemm1_mma() {
    const int e     = blockIdx.z;
    const int mcnt  = g_count[e];
    const int mbase = blockIdx.x * TILE_M;
    if (mbase >= mcnt) return;
    const int nbase = blockIdx.y * TILE_N;

    extern __shared__ char smem_raw[];
    const uint32_t sb = smem_u32(smem_raw);
    const int tid = threadIdx.x, wid = tid >> 5, lane = tid & 31;
    const int hoff = g_offset[e];

    GemmCtx ctx;
    {
        const int r0 = tid >> 3, q = tid & 7;
        const float* Wt = g_w1t + (size_t)e * HIDDEN * D_MODEL;
        const int* tks = g_tok + e * T_TOKENS;
#pragma unroll
        for (int i = 0; i < 4; i++) {
            int r = r0 + 32 * i;
            int gm = mbase + r; if (gm >= mcnt) gm = mcnt - 1;
            ctx.aptr[i] = g_xr + (size_t)tks[gm] * D_MODEL + q * 4;
            ctx.bptr[i] = Wt + (size_t)(nbase + r) * D_MODEL + q * 4;
            ctx.dA[i] = sb + SMEM_A + r * ROWB + q * 16;
            ctx.dB[i] = sb + SMEM_B + r * ROWB + q * 16;
        }
    }

    float acc[4][4][4];
#pragma unroll
    for (int mi = 0; mi < 4; mi++)
#pragma unroll
        for (int ni = 0; ni < 4; ni++)
#pragma unroll
            for (int k = 0; k < 4; k++) acc[mi][ni][k] = 0.f;

    gemm_mainloop(smem_raw, ctx, D_MODEL / TBK, acc, wid, lane);

    // epilogue: SiLU + tf32 round -> g_h
    const int warpM = wid & 1, warpN = wid >> 1;
    const int rb = mbase + warpM * 64 + (lane >> 2);
    const int cb = nbase + warpN * 32 + (lane & 3) * 2;
#pragma unroll
    for (int mi = 0; mi < 4; mi++) {
#pragma unroll
        for (int half = 0; half < 2; half++) {
            const int gm = rb + mi * 16 + half * 8;
            if (gm < mcnt) {
                float* hp = g_h + (size_t)(hoff + gm) * HIDDEN + cb;
#pragma unroll
                for (int ni = 0; ni < 4; ni++) {
                    float v0 = acc[mi][ni][half * 2];
                    float v1 = acc[mi][ni][half * 2 + 1];
                    v0 = to_tf32(v0 / (1.0f + __expf(-v0)));
                    v1 = to_tf32(v1 / (1.0f + __expf(-v1)));
                    *(float2*)(hp + ni * 8) = make_float2(v0, v1);
                }
            }
        }
    }
}

// ---------------- kernel 4: GEMM2 + weighted atomic scatter ----------------
__global__ void __launch_bounds__(256, 2)
gemm2_mma(float* __restrict__ out) {
    const int e     = blockIdx.z;
    const int mcnt  = g_count[e];
    const int mbase = blockIdx.x * TILE_M;
    if (mbase >= mcnt) return;
    const int nbase = blockIdx.y * TILE_N;

    extern __shared__ char smem_raw[];
    const uint32_t sb = smem_u32(smem_raw);
    const int tid = threadIdx.x, wid = tid >> 5, lane = tid & 31;
    const int hoff = g_offset[e];

    GemmCtx ctx;
    {
        const int r0 = tid >> 3, q = tid & 7;
        const float* Wt = g_w2t + (size_t)e * D_MODEL * HIDDEN;
#pragma unroll
        for (int i = 0; i < 4; i++) {
            int r = r0 + 32 * i;
            int gm = mbase + r; if (gm >= mcnt) gm = mcnt - 1;
            ctx.aptr[i] = g_h + (size_t)(hoff + gm) * HIDDEN + q * 4;
            ctx.bptr[i] = Wt + (size_t)(nbase + r) * HIDDEN + q * 4;
            ctx.dA[i] = sb + SMEM_A + r * ROWB + q * 16;
            ctx.dB[i] = sb + SMEM_B + r * ROWB + q * 16;
        }
    }

    float acc[4][4][4];
#pragma unroll
    for (int mi = 0; mi < 4; mi++)
#pragma unroll
        for (int ni = 0; ni < 4; ni++)
#pragma unroll
            for (int k = 0; k < 4; k++) acc[mi][ni][k] = 0.f;

    gemm_mainloop(smem_raw, ctx, HIDDEN / TBK, acc, wid, lane);

    // epilogue: weighted atomic scatter-add into out
    const int warpM = wid & 1, warpN = wid >> 1;
    const int rb = mbase + warpM * 64 + (lane >> 2);
    const int cb = nbase + warpN * 32 + (lane & 3) * 2;
    const int* tks = g_tok + e * T_TOKENS;
    const float* wts = g_wt + e * T_TOKENS;
#pragma unroll
    for (int mi = 0; mi < 4; mi++) {
#pragma unroll
        for (int half = 0; half < 2; half++) {
            const int gm = rb + mi * 16 + half * 8;
            if (gm < mcnt) {
                const int tok = tks[gm];
                const float w = wts[gm];
                float* op = out + (size_t)tok * D_MODEL + cb;
#pragma unroll
                for (int ni = 0; ni < 4; ni++) {
                    atomicAdd(op + ni * 8,     w * acc[mi][ni][half * 2]);
                    atomicAdd(op + ni * 8 + 1, w * acc[mi][ni][half * 2 + 1]);
                }
            }
        }
    }
}

// ---------------- launch ----------------
extern "C" void kernel_launch(void* const* d_in, const int* in_sizes, int n_in,
                              void* d_out, int out_size) {
    const float* x  = (const float*)d_in[0];
    const float* gw = (const float*)d_in[1];
    const float* w1 = (const float*)d_in[2];
    const float* w2 = (const float*)d_in[3];
    float* out = (float*)d_out;

    static bool attr_done = false;
    if (!attr_done) {
        cudaFuncSetAttribute(gemm1_mma, cudaFuncAttributeMaxDynamicSharedMemorySize, SMEM_TOTAL);
        cudaFuncSetAttribute(gemm2_mma, cudaFuncAttributeMaxDynamicSharedMemorySize, SMEM_TOTAL);
        attr_done = true;
    }

    int n4 = out_size / 4;
    zero_kernel<<<(n4 + 255) / 256, 256>>>((float4*)out, n4);
    round_x_kernel<<<(T_TOKENS * D_MODEL + 255) / 256, 256>>>(x);
    {
        dim3 g(HIDDEN / 32, HIDDEN / 32, 2 * N_EXPERTS);
        transpose_w_kernel<<<g, dim3(32, 8)>>>(w1, w2);
    }
    gate_kernel<<<T_TOKENS / 8, 256>>>(x, gw);
    scan_kernel<<<1, 32>>>();

    dim3 g1(T_TOKENS / TILE_M, HIDDEN / TILE_N, N_EXPERTS);   // (128, 32, 8)
    gemm1_mma<<<g1, 256, SMEM_TOTAL>>>();

    dim3 g2(T_TOKENS / TILE_M, D_MODEL / TILE_N, N_EXPERTS);  // (128, 8, 8)
    gemm2_mma<<<g2, 256, SMEM_TOTAL>>>(out);
}